// round 6
// baseline (speedup 1.0000x reference)
#include <cuda_runtime.h>
#include <cuda_fp16.h>
#include <math.h>
#include <stdint.h>

// ---------------- problem constants ----------------
#define BATCH 2
#define SEQ   2048
#define DM    5120
#define NH    8
#define DH    640
#define DR    16
#define SPLITD 624
#define DKV   128
#define MROWS (BATCH*SEQ)        // 4096
#define NCOMP (NH*SPLITD)        // 4992
#define NKV   (NCOMP+DKV+DM)     // 10240 : [uk | kr | uv]
#define NQM   (NCOMP+DKV)        // 5120  : [uq | qr]

// ---------------- scratch (device globals; no allocs allowed) ----------------
__device__ __align__(16) __half g_hh   [(size_t)MROWS*DM];
__device__ __align__(16) __half g_ckvh [MROWS*DKV];
__device__ __align__(16) __half g_cqh  [MROWS*DKV];
__device__ __align__(16) __half g_kvout[(size_t)MROWS*NKV];   // merged k-side up-proj
__device__ __align__(16) __half g_qout [(size_t)MROWS*NQM];   // merged q-side up-proj
__device__ __align__(16) __half g_q    [(size_t)MROWS*DM];
__device__ __align__(16) __half g_k    [(size_t)MROWS*DM];
__device__ __align__(16) __half g_vt   [(size_t)MROWS*DM];
__device__ __align__(16) __half g_ao   [(size_t)MROWS*DM];
__device__ __align__(16) __half g_sc   [(size_t)BATCH*NH*SEQ*SEQ];   // 128 MB
__device__ __align__(16) float  g_ckvf [MROWS*DKV];
// transposed weights, half
__device__ __align__(16) __half g_wt_dkv[DKV*DM];
__device__ __align__(16) __half g_wt_dq [DKV*DM];
__device__ __align__(16) __half g_wt_kv [(size_t)NKV*DKV];    // [uk|kr|uv] rows, K-major
__device__ __align__(16) __half g_wt_q  [(size_t)NQM*DKV];    // [uq|qr]
__device__ __align__(16) __half g_wt_out[(size_t)DM*DM];
__device__ __align__(16) float  g_bias_kv[NKV];
__device__ __align__(16) float  g_bias_q [NQM];

// ---------------- PTX helpers ----------------
__device__ __forceinline__ uint32_t smem_u32(const void* p) {
    uint32_t a;
    asm("{ .reg .u64 t; cvta.to.shared.u64 t, %1; cvt.u32.u64 %0, t; }" : "=r"(a) : "l"(p));
    return a;
}
__device__ __forceinline__ void cp16(uint32_t dst, const void* src) {
    asm volatile("cp.async.cg.shared.global [%0], [%1], 16;" :: "r"(dst), "l"(src) : "memory");
}
#define CP_COMMIT() asm volatile("cp.async.commit_group;" ::: "memory")
#define CP_WAIT(n)  asm volatile("cp.async.wait_group %0;" :: "n"(n) : "memory")

__device__ __forceinline__ void ldm_x4(uint32_t* r, uint32_t addr) {
    asm volatile("ldmatrix.sync.aligned.m8n8.x4.shared.b16 {%0,%1,%2,%3}, [%4];"
                 : "=r"(r[0]), "=r"(r[1]), "=r"(r[2]), "=r"(r[3]) : "r"(addr));
}
__device__ __forceinline__ void mma_f16(float* c, const uint32_t* a, uint32_t b0, uint32_t b1) {
    asm volatile("mma.sync.aligned.m16n8k16.row.col.f32.f16.f16.f32 "
                 "{%0,%1,%2,%3}, {%4,%5,%6,%7}, {%8,%9}, {%0,%1,%2,%3};"
                 : "+f"(c[0]), "+f"(c[1]), "+f"(c[2]), "+f"(c[3])
                 : "r"(a[0]), "r"(a[1]), "r"(a[2]), "r"(a[3]), "r"(b0), "r"(b1));
}

// ============================================================================
// fp16 mma.sync GEMM: C[M,N] = alpha * A[M,K] * B[N,K]^T (+ bias)
// 128x128 CTA tile, BK=64, 3-stage cp.async ring, one __syncthreads per iter.
// M%128==0, N%128==0, K%64==0. 256 threads.
// ============================================================================
#define BKH 64
#define SPADH 72                 // 64 + 8 halfs pad -> 144B rows, conflict-free
#define STG_HALFS (128*SPADH)    // 9216 halfs per operand per stage
#define SMEM_H (3*2*STG_HALFS*2) // 110592 bytes

__global__ __launch_bounds__(256)
void hgemm(const __half* __restrict__ A, const __half* __restrict__ B,
           float* __restrict__ Cf, __half* __restrict__ Ch,
           const float* __restrict__ bias,
           int M, int N, int K, int lda, int ldb, int ldc, float alpha,
           long long sAhi, long long sAlo, long long sBhi, long long sBlo,
           long long sChi, long long sClo, int zdiv)
{
    extern __shared__ __half smp[];
    __half* Asm = smp;                       // [3][128][SPADH]
    __half* Bsm = smp + 3 * STG_HALFS;

    int tid  = threadIdx.x;
    int warp = tid >> 5;
    int lane = tid & 31;
    int wr = warp >> 1;          // 0..3
    int wc = warp & 1;           // 0..1
    int qid = lane >> 2;         // 0..7
    int tig = lane & 3;          // 0..3

    int z  = blockIdx.z;
    int zh = z / zdiv, zl = z % zdiv;
    A += zh * sAhi + zl * sAlo;
    B += zh * sBhi + zl * sBlo;
    long long cofs = zh * sChi + zl * sClo;
    if (Cf) Cf += cofs;
    if (Ch) Ch += cofs;

    int row0 = blockIdx.y * 128, col0 = blockIdx.x * 128;
    const __half* Ab = A + (size_t)row0 * lda;
    const __half* Bb = B + (size_t)col0 * ldb;

    // cp.async coords: 1024 chunks (8 halfs) per operand per tile, 4 per thread
    int lr[4], lc[4];
#pragma unroll
    for (int i = 0; i < 4; i++) {
        int idx = tid + i * 256;
        lr[i] = idx >> 3;
        lc[i] = (idx & 7) * 8;
    }
    uint32_t dstA[3][4], dstB[3][4];
#pragma unroll
    for (int s = 0; s < 3; s++)
#pragma unroll
        for (int i = 0; i < 4; i++) {
            dstA[s][i] = smem_u32(Asm + s * STG_HALFS + lr[i] * SPADH + lc[i]);
            dstB[s][i] = smem_u32(Bsm + s * STG_HALFS + lr[i] * SPADH + lc[i]);
        }
    // ldmatrix base addresses per stage
    uint32_t aAddr[3][2], bAddr[3][4];
#pragma unroll
    for (int s = 0; s < 3; s++) {
#pragma unroll
        for (int mi = 0; mi < 2; mi++)
            aAddr[s][mi] = smem_u32(Asm + s * STG_HALFS
                + (wr * 32 + mi * 16 + (lane & 15)) * SPADH + (lane >> 4) * 8);
#pragma unroll
        for (int np = 0; np < 4; np++)
            bAddr[s][np] = smem_u32(Bsm + s * STG_HALFS
                + (wc * 64 + np * 16 + (lane & 7) + ((lane >> 4) & 1) * 8) * SPADH
                + ((lane >> 3) & 1) * 8);
    }

    float acc[2][8][4];
#pragma unroll
    for (int mi = 0; mi < 2; mi++)
#pragma unroll
        for (int ni = 0; ni < 8; ni++)
#pragma unroll
            for (int i = 0; i < 4; i++) acc[mi][ni][i] = 0.0f;

    int T = K / BKH;

    // prologue: tiles 0 and 1
#pragma unroll
    for (int p = 0; p < 2; p++) {
        int k0 = p * BKH;
#pragma unroll
        for (int i = 0; i < 4; i++) {
            cp16(dstA[p][i], Ab + (size_t)lr[i] * lda + k0 + lc[i]);
            cp16(dstB[p][i], Bb + (size_t)lr[i] * ldb + k0 + lc[i]);
        }
        CP_COMMIT();
    }

    for (int t = 0; t < T; t++) {
        if (t + 1 < T) { CP_WAIT(1); } else { CP_WAIT(0); }
        __syncthreads();

        if (t + 2 < T) {
            int s = (t + 2) % 3;
            int k0 = (t + 2) * BKH;
#pragma unroll
            for (int i = 0; i < 4; i++) {
                cp16(dstA[s][i], Ab + (size_t)lr[i] * lda + k0 + lc[i]);
                cp16(dstB[s][i], Bb + (size_t)lr[i] * ldb + k0 + lc[i]);
            }
            CP_COMMIT();
        }

        int s = t % 3;
#pragma unroll
        for (int ks = 0; ks < 4; ks++) {
            uint32_t koff = ks * 32;  // 16 halfs = 32 bytes
            uint32_t a[2][4], b[16];
#pragma unroll
            for (int mi = 0; mi < 2; mi++) ldm_x4(a[mi], aAddr[s][mi] + koff);
#pragma unroll
            for (int np = 0; np < 4; np++) ldm_x4(b + np * 4, bAddr[s][np] + koff);
#pragma unroll
            for (int ni = 0; ni < 8; ni++) {
                uint32_t b0 = b[(ni >> 1) * 4 + (ni & 1) * 2];
                uint32_t b1 = b[(ni >> 1) * 4 + (ni & 1) * 2 + 1];
                mma_f16(acc[0][ni], a[0], b0, b1);
                mma_f16(acc[1][ni], a[1], b0, b1);
            }
        }
    }

    // epilogue
#pragma unroll
    for (int mi = 0; mi < 2; mi++) {
        int rg = row0 + wr * 32 + mi * 16 + qid;
#pragma unroll
        for (int ni = 0; ni < 8; ni++) {
            int cg = col0 + wc * 64 + ni * 8 + tig * 2;
            float bx = 0.0f, by = 0.0f;
            if (bias) { bx = bias[cg]; by = bias[cg + 1]; }
            float o0 = alpha * acc[mi][ni][0] + bx;
            float o1 = alpha * acc[mi][ni][1] + by;
            float o2 = alpha * acc[mi][ni][2] + bx;
            float o3 = alpha * acc[mi][ni][3] + by;
            if (Cf) {
                *reinterpret_cast<float2*>(Cf + (size_t)rg * ldc + cg)       = make_float2(o0, o1);
                *reinterpret_cast<float2*>(Cf + (size_t)(rg + 8) * ldc + cg) = make_float2(o2, o3);
            }
            if (Ch) {
                *reinterpret_cast<__half2*>(Ch + (size_t)rg * ldc + cg)       = __floats2half2_rn(o0, o1);
                *reinterpret_cast<__half2*>(Ch + (size_t)(rg + 8) * ldc + cg) = __floats2half2_rn(o2, o3);
            }
        }
    }
}

// ============================================================================
// transposes / packs
// ============================================================================
__global__ __launch_bounds__(256)
void transpose_f2h(const float* __restrict__ in, __half* __restrict__ out, int ldi, int ldo)
{
    __shared__ float t[32][33];
    int bx = blockIdx.x * 32, by = blockIdx.y * 32;
    int tx = threadIdx.x & 31, ty = threadIdx.x >> 5;
#pragma unroll
    for (int i = 0; i < 4; i++)
        t[ty + 8 * i][tx] = in[(size_t)(by + ty + 8 * i) * ldi + bx + tx];
    __syncthreads();
#pragma unroll
    for (int i = 0; i < 4; i++)
        out[(size_t)(bx + ty + 8 * i) * ldo + by + tx] = __float2half_rn(t[tx][ty + 8 * i]);
}

__global__ __launch_bounds__(256)
void transpose_h2h(const __half* __restrict__ in, __half* __restrict__ out,
                   int ldi, int ldo,
                   long long siHi, long long siLo, long long soHi, long long soLo, int zdiv)
{
    int z = blockIdx.z;
    in  += (z / zdiv) * siHi + (z % zdiv) * siLo;
    out += (z / zdiv) * soHi + (z % zdiv) * soLo;
    __shared__ __half t[32][34];
    int bx = blockIdx.x * 32, by = blockIdx.y * 32;
    int tx = threadIdx.x & 31, ty = threadIdx.x >> 5;
#pragma unroll
    for (int i = 0; i < 4; i++)
        t[ty + 8 * i][tx] = in[(size_t)(by + ty + 8 * i) * ldi + bx + tx];
    __syncthreads();
#pragma unroll
    for (int i = 0; i < 4; i++)
        out[(size_t)(bx + ty + 8 * i) * ldo + by + tx] = t[tx][ty + 8 * i];
}

__global__ void f2h_k(const float* __restrict__ in, __half* __restrict__ out, int n4)
{
    int i = blockIdx.x * blockDim.x + threadIdx.x;
    if (i >= n4) return;
    float4 v = *reinterpret_cast<const float4*>(in + (size_t)i * 4);
    __half2 a = __floats2half2_rn(v.x, v.y);
    __half2 b = __floats2half2_rn(v.z, v.w);
    *reinterpret_cast<uint2*>(out + (size_t)i * 4) = make_uint2(
        *reinterpret_cast<uint32_t*>(&a), *reinterpret_cast<uint32_t*>(&b));
}

// pack compact base cols [m, 0..4991] of a [m, lds] buffer -> [m,5120] head layout
__global__ void pack_k(const __half* __restrict__ src, __half* __restrict__ dst, int lds)
{
    int idx = blockIdx.x * blockDim.x + threadIdx.x;   // 8-half chunk index
    if (idx >= MROWS * (NCOMP / 8)) return;
    int m = idx / (NCOMP / 8);
    int q = idx % (NCOMP / 8);
    int h = q / (SPLITD / 8);
    int j = q % (SPLITD / 8);
    uint4 v = *reinterpret_cast<const uint4*>(src + (size_t)m * lds + q * 8);
    *reinterpret_cast<uint4*>(dst + (size_t)m * DM + h * DH + j * 8) = v;
}

// RoPE: rot region is cols [0..127] of a strided buffer (stride lds)
__global__ void rope_k(const __half* __restrict__ rot, int lds, __half* __restrict__ dst,
                       float* __restrict__ rout)
{
    int idx = blockIdx.x * blockDim.x + threadIdx.x;
    if (idx >= MROWS * DKV) return;
    int m = idx >> 7;
    int c = idx & 127;
    int h = c >> 4;
    int d = c & 15;
    int j = d & 7;
    int s = m & (SEQ - 1);
    float t = (float)s * (1.0f / 40.0f);
    float invf = __expf(-(float)j * 0.86346941f);  // ln(1000)/8
    float ang = t * invf;
    float sn, cs;
    sincosf(ang, &sn, &cs);
    float x = __half2float(rot[(size_t)m * lds + c]);
    float p = __half2float(rot[(size_t)m * lds + (h << 4) + ((d < 8) ? d + 8 : d - 8)]);
    float val = x * cs + ((d < 8) ? -p : p) * sn;
    dst[(size_t)m * DM + h * DH + SPLITD + d] = __float2half_rn(val);
    if (rout) rout[idx] = val;
}

// bias packing
__global__ void bias_pack_kv(const float* a, const float* b, const float* c, float* o)
{
    int i = blockIdx.x * blockDim.x + threadIdx.x;
    if (i >= NKV) return;
    o[i] = (i < NCOMP) ? a[i] : (i < NCOMP + DKV ? b[i - NCOMP] : c[i - NCOMP - DKV]);
}
__global__ void bias_pack_q(const float* a, const float* b, float* o)
{
    int i = blockIdx.x * blockDim.x + threadIdx.x;
    if (i >= NQM) return;
    o[i] = (i < NCOMP) ? a[i] : b[i - NCOMP];
}

// ---------------- softmax over rows of length SEQ (half) ----------------
__global__ __launch_bounds__(256) void softmax_k(__half* __restrict__ s)
{
    __half2* row = reinterpret_cast<__half2*>(s + (size_t)blockIdx.x * SEQ);
    int t = threadIdx.x;
    float v[8];
    float mx = -1e30f;
#pragma unroll
    for (int i = 0; i < 4; i++) {
        float2 f = __half22float2(row[t + i * 256]);
        v[2 * i] = f.x; v[2 * i + 1] = f.y;
        mx = fmaxf(mx, fmaxf(f.x, f.y));
    }
    __shared__ float red[256];
    red[t] = mx; __syncthreads();
    for (int off = 128; off > 0; off >>= 1) {
        if (t < off) red[t] = fmaxf(red[t], red[t + off]);
        __syncthreads();
    }
    mx = red[0]; __syncthreads();
    float sum = 0.0f;
#pragma unroll
    for (int i = 0; i < 8; i++) { v[i] = __expf(v[i] - mx); sum += v[i]; }
    red[t] = sum; __syncthreads();
    for (int off = 128; off > 0; off >>= 1) {
        if (t < off) red[t] += red[t + off];
        __syncthreads();
    }
    float inv = 1.0f / red[0];
#pragma unroll
    for (int i = 0; i < 4; i++)
        row[t + i * 256] = __floats2half2_rn(v[2 * i] * inv, v[2 * i + 1] * inv);
}

// ============================================================================
// host launcher
// ============================================================================
extern "C" void kernel_launch(void* const* d_in, const int* in_sizes, int n_in,
                              void* d_out, int out_size)
{
    const float* h    = (const float*)d_in[0];
    const float* Wdkv = (const float*)d_in[1];
    const float* bdkv = (const float*)d_in[2];
    const float* Wdq  = (const float*)d_in[3];
    const float* bdq  = (const float*)d_in[4];
    const float* Wuk  = (const float*)d_in[5];
    const float* buk  = (const float*)d_in[6];
    const float* Wuv  = (const float*)d_in[7];
    const float* buv  = (const float*)d_in[8];
    const float* Wuq  = (const float*)d_in[9];
    const float* buq  = (const float*)d_in[10];
    const float* Wqr  = (const float*)d_in[11];
    const float* bqr  = (const float*)d_in[12];
    const float* Wkr  = (const float*)d_in[13];
    const float* bkr  = (const float*)d_in[14];
    const float* outw = (const float*)d_in[15];
    const float* outb = (const float*)d_in[16];
    float* out = (float*)d_out;

    __half *hh, *ckvh, *cqh, *kvout, *qout, *qb, *kb, *vt, *ao, *sc;
    __half *wt_dkv, *wt_dq, *wt_kv, *wt_q, *wt_out;
    float *ckvf, *bias_kv, *bias_q;
    cudaGetSymbolAddress((void**)&hh,    g_hh);
    cudaGetSymbolAddress((void**)&ckvh,  g_ckvh);
    cudaGetSymbolAddress((void**)&cqh,   g_cqh);
    cudaGetSymbolAddress((void**)&kvout, g_kvout);
    cudaGetSymbolAddress((void**)&qout,  g_qout);
    cudaGetSymbolAddress((void**)&qb,    g_q);
    cudaGetSymbolAddress((void**)&kb,    g_k);
    cudaGetSymbolAddress((void**)&vt,    g_vt);
    cudaGetSymbolAddress((void**)&ao,    g_ao);
    cudaGetSymbolAddress((void**)&sc,    g_sc);
    cudaGetSymbolAddress((void**)&ckvf,  g_ckvf);
    cudaGetSymbolAddress((void**)&wt_dkv, g_wt_dkv);
    cudaGetSymbolAddress((void**)&wt_dq,  g_wt_dq);
    cudaGetSymbolAddress((void**)&wt_kv,  g_wt_kv);
    cudaGetSymbolAddress((void**)&wt_q,   g_wt_q);
    cudaGetSymbolAddress((void**)&wt_out, g_wt_out);
    cudaGetSymbolAddress((void**)&bias_kv, g_bias_kv);
    cudaGetSymbolAddress((void**)&bias_q,  g_bias_q);

    cudaFuncSetAttribute(hgemm, cudaFuncAttributeMaxDynamicSharedMemorySize, SMEM_H);

    dim3 b256(256);
    // ---- input conversion + weight transposes into merged layouts ----
    f2h_k<<<((size_t)MROWS * DM / 4 + 255) / 256, 256>>>(h, hh, MROWS * DM / 4);
    transpose_f2h<<<dim3(DKV/32, DM/32), b256>>>(Wdkv, wt_dkv, DKV, DM);
    transpose_f2h<<<dim3(DKV/32, DM/32), b256>>>(Wdq,  wt_dq,  DKV, DM);
    transpose_f2h<<<dim3(NCOMP/32, DKV/32), b256>>>(Wuk, wt_kv,                       NCOMP, DKV);
    transpose_f2h<<<dim3(DKV/32,   DKV/32), b256>>>(Wkr, wt_kv + (size_t)NCOMP*DKV,   DKV,   DKV);
    transpose_f2h<<<dim3(DM/32,    DKV/32), b256>>>(Wuv, wt_kv + (size_t)(NCOMP+DKV)*DKV, DM, DKV);
    transpose_f2h<<<dim3(NCOMP/32, DKV/32), b256>>>(Wuq, wt_q,                        NCOMP, DKV);
    transpose_f2h<<<dim3(DKV/32,   DKV/32), b256>>>(Wqr, wt_q + (size_t)NCOMP*DKV,    DKV,   DKV);
    transpose_f2h<<<dim3(DM/32, DM/32), b256>>>(outw, wt_out, DM, DM);
    bias_pack_kv<<<(NKV + 255) / 256, 256>>>(buk, bkr, buv, bias_kv);
    bias_pack_q<<<(NQM + 255) / 256, 256>>>(buq, bqr, bias_q);

    const size_t out_ckv_off  = (size_t)MROWS * DM;
    const size_t out_krot_off = out_ckv_off + (size_t)MROWS * DKV;
    bool full_out = (size_t)out_size >= out_krot_off + (size_t)MROWS * DKV;
    float* ckv_dst = full_out ? (out + out_ckv_off) : ckvf;

    dim3 blk(256);
    auto grd = [](int M, int N, int Z) { return dim3((unsigned)(N / 128), (unsigned)(M / 128), (unsigned)Z); };

    // 1) down projections
    hgemm<<<grd(MROWS, DKV, 1), blk, SMEM_H>>>(hh, wt_dkv, ckv_dst, ckvh, bdkv,
        MROWS, DKV, DM, DM, DM, DKV, 1.0f, 0,0,0,0,0,0, 1);
    hgemm<<<grd(MROWS, DKV, 1), blk, SMEM_H>>>(hh, wt_dq, nullptr, cqh, bdq,
        MROWS, DKV, DM, DM, DM, DKV, 1.0f, 0,0,0,0,0,0, 1);

    // 2) merged up projections
    hgemm<<<grd(MROWS, NKV, 1), blk, SMEM_H>>>(ckvh, wt_kv, nullptr, kvout, bias_kv,
        MROWS, NKV, DKV, DKV, DKV, NKV, 1.0f, 0,0,0,0,0,0, 1);
    hgemm<<<grd(MROWS, NQM, 1), blk, SMEM_H>>>(cqh, wt_q, nullptr, qout, bias_q,
        MROWS, NQM, DKV, DKV, DKV, NQM, 1.0f, 0,0,0,0,0,0, 1);

    // pack base parts into [*,5120] head layout
    pack_k<<<(MROWS * (NCOMP/8) + 255) / 256, 256>>>(kvout, kb, NKV);
    pack_k<<<(MROWS * (NCOMP/8) + 255) / 256, 256>>>(qout,  qb, NQM);

    // 3) RoPE (+ float k_rot output)
    rope_k<<<(MROWS * DKV + 255) / 256, 256>>>(qout + NCOMP, NQM, qb, nullptr);
    rope_k<<<(MROWS * DKV + 255) / 256, 256>>>(kvout + NCOMP, NKV, kb,
        full_out ? (out + out_krot_off) : nullptr);

    // V region of kvout (cols 5120..10239): transpose per (b,h) to [640,2048]
    const long long SDM = (long long)SEQ * DM;
    const long long HDS = (long long)DH * SEQ;
    transpose_h2h<<<dim3(DH/32, SEQ/32, BATCH*NH), b256>>>(kvout + (NCOMP + DKV), vt, NKV, SEQ,
        (long long)SEQ * NKV, DH, (long long)NH * HDS, HDS, NH);

    // 4) attention scores
    const long long SS = (long long)SEQ * SEQ;
    float inv_sqrt = 1.0f / sqrtf((float)DH);
    hgemm<<<grd(SEQ, SEQ, BATCH*NH), blk, SMEM_H>>>(qb, kb, nullptr, sc, nullptr,
        SEQ, SEQ, DH, DM, DM, SEQ, inv_sqrt,
        SDM, DH, SDM, DH, (long long)NH * SS, SS, NH);

    // 5) softmax
    softmax_k<<<BATCH * NH * SEQ, 256>>>(sc);

    // 6) attn @ v
    hgemm<<<grd(SEQ, DH, BATCH*NH), blk, SMEM_H>>>(sc, vt, nullptr, ao, nullptr,
        SEQ, DH, SEQ, SEQ, SEQ, DM, 1.0f,
        (long long)NH * SS, SS, (long long)NH * HDS, HDS, SDM, DH, NH);

    // 7) output projection -> float out
    hgemm<<<grd(MROWS, DM, 1), blk, SMEM_H>>>(ao, wt_out, out, nullptr, outb,
        MROWS, DM, DM, DM, DM, DM, 1.0f, 0,0,0,0,0,0, 1);
}

// round 7
// speedup vs baseline: 1.1726x; 1.1726x over previous
#include <cuda_runtime.h>
#include <cuda_fp16.h>
#include <math.h>
#include <stdint.h>

// ---------------- problem constants ----------------
#define BATCH 2
#define SEQ   2048
#define DM    5120
#define NH    8
#define DH    640
#define DR    16
#define SPLITD 624
#define DKV   128
#define MROWS (BATCH*SEQ)        // 4096
#define KP    160                // padded per-head score K-dim: [128 ckv |16 rope |1 bias |15 pad]
#define LDQP  (NH*KP)            // 1280

// ---------------- scratch (device globals; no allocs allowed) ----------------
__device__ __align__(16) __half g_hh   [(size_t)MROWS*DM];
__device__ __align__(16) __half g_ckvh [MROWS*DKV];
__device__ __align__(16) __half g_cqh  [MROWS*DKV];
__device__ __align__(16) __half g_ckvt [BATCH*DKV*SEQ];
__device__ __align__(16) __half g_qrp  [MROWS*DKV];
__device__ __align__(16) __half g_krp  [MROWS*DKV];
__device__ __align__(16) __half g_qp   [(size_t)MROWS*LDQP];
__device__ __align__(16) __half g_kp   [(size_t)MROWS*LDQP];
__device__ __align__(16) __half g_sc   [(size_t)BATCH*NH*SEQ*SEQ];   // 128 MB
__device__ __align__(16) __half g_u    [(size_t)MROWS*NH*DKV];       // [4096,1024]
__device__ __align__(16) float  g_ckvf [MROWS*DKV];
// weights
__device__ __align__(16) __half g_wt_dkv[DKV*DM];
__device__ __align__(16) __half g_wt_dq [DKV*DM];
__device__ __align__(16) __half g_wt_qr [DKV*DKV];
__device__ __align__(16) __half g_wt_kr [DKV*DKV];
__device__ __align__(16) __half g_wt_out[(size_t)DM*DM];   // Wout^T [DM, NH*DH]
__device__ __align__(16) __half g_wuv_h [DKV*DM];          // Wuv as-is, half
__device__ __align__(16) __half g_wuq_p [DKV*NH*DH];       // zero-padded 624->640
__device__ __align__(16) __half g_wuk_p [DKV*NH*DH];
__device__ __align__(16) __half g_mt    [NH*DKV*DKV];      // Mt_h = Wuk_h Wuq_h^T
__device__ __align__(16) __half g_w2t   [(size_t)DM*NH*DKV]; // [5120,1024]
__device__ __align__(16) float  g_bias2 [DM];
__device__ __align__(16) float  g_bqrow [NH*DKV];
__device__ __align__(16) float  g_wh    [NH*DKV];
__device__ __align__(16) float  g_sconst[NH];

// ---------------- PTX helpers ----------------
__device__ __forceinline__ uint32_t smem_u32(const void* p) {
    uint32_t a;
    asm("{ .reg .u64 t; cvta.to.shared.u64 t, %1; cvt.u32.u64 %0, t; }" : "=r"(a) : "l"(p));
    return a;
}
__device__ __forceinline__ void cp16(uint32_t dst, const void* src) {
    asm volatile("cp.async.cg.shared.global [%0], [%1], 16;" :: "r"(dst), "l"(src) : "memory");
}
#define CP_COMMIT() asm volatile("cp.async.commit_group;" ::: "memory")
#define CP_WAIT(n)  asm volatile("cp.async.wait_group %0;" :: "n"(n) : "memory")

__device__ __forceinline__ void ldm_x4(uint32_t* r, uint32_t addr) {
    asm volatile("ldmatrix.sync.aligned.m8n8.x4.shared.b16 {%0,%1,%2,%3}, [%4];"
                 : "=r"(r[0]), "=r"(r[1]), "=r"(r[2]), "=r"(r[3]) : "r"(addr));
}
__device__ __forceinline__ void mma_f16(float* c, const uint32_t* a, uint32_t b0, uint32_t b1) {
    asm volatile("mma.sync.aligned.m16n8k16.row.col.f32.f16.f16.f32 "
                 "{%0,%1,%2,%3}, {%4,%5,%6,%7}, {%8,%9}, {%0,%1,%2,%3};"
                 : "+f"(c[0]), "+f"(c[1]), "+f"(c[2]), "+f"(c[3])
                 : "r"(a[0]), "r"(a[1]), "r"(a[2]), "r"(a[3]), "r"(b0), "r"(b1));
}

// ============================================================================
// fp16 mma.sync GEMM (R5 config): C[M,N] = alpha * A[M,K] * B[N,K]^T (+ bias)
// 128x128 CTA tile, BK=32, 2-stage cp.async. M%128==0, N%128==0, K%32==0.
// ============================================================================
#define SPADH 40

__global__ __launch_bounds__(256)
void hgemm(const __half* __restrict__ A, const __half* __restrict__ B,
           float* __restrict__ Cf, __half* __restrict__ Ch,
           const float* __restrict__ bias,
           int M, int N, int K, int lda, int ldb, int ldc, float alpha,
           long long sAhi, long long sAlo, long long sBhi, long long sBlo,
           long long sChi, long long sClo, long long sBiasLo, int zdiv)
{
    __shared__ __half As[2][128][SPADH];
    __shared__ __half Bs[2][128][SPADH];

    int tid  = threadIdx.x;
    int warp = tid >> 5;
    int lane = tid & 31;
    int wr = warp >> 1;
    int wc = warp & 1;
    int qid = lane >> 2;
    int tig = lane & 3;

    int z  = blockIdx.z;
    int zh = z / zdiv, zl = z % zdiv;
    A += zh * sAhi + zl * sAlo;
    B += zh * sBhi + zl * sBlo;
    long long cofs = zh * sChi + zl * sClo;
    if (Cf) Cf += cofs;
    if (Ch) Ch += cofs;
    if (bias) bias += zl * sBiasLo;

    int row0 = blockIdx.y * 128, col0 = blockIdx.x * 128;
    const __half* Ab = A + (size_t)row0 * lda;
    const __half* Bb = B + (size_t)col0 * ldb;

    int r0 = tid >> 2, cc = (tid & 3) * 8;
    int r1 = r0 + 64;
    uint32_t dA0[2], dA1[2], dB0[2], dB1[2];
#pragma unroll
    for (int s = 0; s < 2; s++) {
        dA0[s] = smem_u32(&As[s][r0][cc]);
        dA1[s] = smem_u32(&As[s][r1][cc]);
        dB0[s] = smem_u32(&Bs[s][r0][cc]);
        dB1[s] = smem_u32(&Bs[s][r1][cc]);
    }
    uint32_t aAddr[2][2], bAddr[2][4];
#pragma unroll
    for (int s = 0; s < 2; s++) {
#pragma unroll
        for (int mi = 0; mi < 2; mi++)
            aAddr[s][mi] = smem_u32(&As[s][wr * 32 + mi * 16 + (lane & 15)][(lane >> 4) * 8]);
#pragma unroll
        for (int np = 0; np < 4; np++)
            bAddr[s][np] = smem_u32(&Bs[s][wc * 64 + np * 16 + (lane & 7) + ((lane >> 4) & 1) * 8]
                                        [((lane >> 3) & 1) * 8]);
    }

    float acc[2][8][4];
#pragma unroll
    for (int mi = 0; mi < 2; mi++)
#pragma unroll
        for (int ni = 0; ni < 8; ni++)
#pragma unroll
            for (int i = 0; i < 4; i++) acc[mi][ni][i] = 0.0f;

    int T = K >> 5;

    cp16(dA0[0], Ab + (size_t)r0 * lda + cc);
    cp16(dA1[0], Ab + (size_t)r1 * lda + cc);
    cp16(dB0[0], Bb + (size_t)r0 * ldb + cc);
    cp16(dB1[0], Bb + (size_t)r1 * ldb + cc);
    CP_COMMIT();

    for (int t = 0; t < T; t++) {
        if (t + 1 < T) {
            int s = (t + 1) & 1;
            int k0 = (t + 1) * 32;
            cp16(dA0[s], Ab + (size_t)r0 * lda + k0 + cc);
            cp16(dA1[s], Ab + (size_t)r1 * lda + k0 + cc);
            cp16(dB0[s], Bb + (size_t)r0 * ldb + k0 + cc);
            cp16(dB1[s], Bb + (size_t)r1 * ldb + k0 + cc);
            CP_COMMIT();
            CP_WAIT(1);
        } else {
            CP_WAIT(0);
        }
        __syncthreads();

        int s = t & 1;
#pragma unroll
        for (int ks = 0; ks < 2; ks++) {
            uint32_t koff = ks * 32;
            uint32_t a[2][4], b[16];
#pragma unroll
            for (int mi = 0; mi < 2; mi++) ldm_x4(a[mi], aAddr[s][mi] + koff);
#pragma unroll
            for (int np = 0; np < 4; np++) ldm_x4(b + np * 4, bAddr[s][np] + koff);
#pragma unroll
            for (int ni = 0; ni < 8; ni++) {
                uint32_t b0 = b[(ni >> 1) * 4 + (ni & 1) * 2];
                uint32_t b1 = b[(ni >> 1) * 4 + (ni & 1) * 2 + 1];
                mma_f16(acc[0][ni], a[0], b0, b1);
                mma_f16(acc[1][ni], a[1], b0, b1);
            }
        }
        __syncthreads();
    }

#pragma unroll
    for (int mi = 0; mi < 2; mi++) {
        int rg = row0 + wr * 32 + mi * 16 + qid;
#pragma unroll
        for (int ni = 0; ni < 8; ni++) {
            int cg = col0 + wc * 64 + ni * 8 + tig * 2;
            float bx = 0.0f, by = 0.0f;
            if (bias) { bx = bias[cg]; by = bias[cg + 1]; }
            float o0 = alpha * acc[mi][ni][0] + bx;
            float o1 = alpha * acc[mi][ni][1] + by;
            float o2 = alpha * acc[mi][ni][2] + bx;
            float o3 = alpha * acc[mi][ni][3] + by;
            if (Cf) {
                *reinterpret_cast<float2*>(Cf + (size_t)rg * ldc + cg)       = make_float2(o0, o1);
                *reinterpret_cast<float2*>(Cf + (size_t)(rg + 8) * ldc + cg) = make_float2(o2, o3);
            }
            if (Ch) {
                *reinterpret_cast<__half2*>(Ch + (size_t)rg * ldc + cg)       = __floats2half2_rn(o0, o1);
                *reinterpret_cast<__half2*>(Ch + (size_t)(rg + 8) * ldc + cg) = __floats2half2_rn(o2, o3);
            }
        }
    }
}

// ============================================================================
// small kernels
// ============================================================================
__global__ __launch_bounds__(256)
void transpose_f2h(const float* __restrict__ in, __half* __restrict__ out, int ldi, int ldo)
{
    __shared__ float t[32][33];
    int bx = blockIdx.x * 32, by = blockIdx.y * 32;
    int tx = threadIdx.x & 31, ty = threadIdx.x >> 5;
#pragma unroll
    for (int i = 0; i < 4; i++)
        t[ty + 8 * i][tx] = in[(size_t)(by + ty + 8 * i) * ldi + bx + tx];
    __syncthreads();
#pragma unroll
    for (int i = 0; i < 4; i++)
        out[(size_t)(bx + ty + 8 * i) * ldo + by + tx] = __float2half_rn(t[tx][ty + 8 * i]);
}

__global__ __launch_bounds__(256)
void transpose_h2h(const __half* __restrict__ in, __half* __restrict__ out,
                   int ldi, int ldo, long long siHi, long long soHi)
{
    int z = blockIdx.z;
    in  += z * siHi;
    out += z * soHi;
    __shared__ __half t[32][34];
    int bx = blockIdx.x * 32, by = blockIdx.y * 32;
    int tx = threadIdx.x & 31, ty = threadIdx.x >> 5;
#pragma unroll
    for (int i = 0; i < 4; i++)
        t[ty + 8 * i][tx] = in[(size_t)(by + ty + 8 * i) * ldi + bx + tx];
    __syncthreads();
#pragma unroll
    for (int i = 0; i < 4; i++)
        out[(size_t)(bx + ty + 8 * i) * ldo + by + tx] = t[tx][ty + 8 * i];
}

__global__ void f2h_k(const float* __restrict__ in, __half* __restrict__ out, int n4)
{
    int i = blockIdx.x * blockDim.x + threadIdx.x;
    if (i >= n4) return;
    float4 v = *reinterpret_cast<const float4*>(in + (size_t)i * 4);
    __half2 a = __floats2half2_rn(v.x, v.y);
    __half2 b = __floats2half2_rn(v.z, v.w);
    *reinterpret_cast<uint2*>(out + (size_t)i * 4) = make_uint2(
        *reinterpret_cast<uint32_t*>(&a), *reinterpret_cast<uint32_t*>(&b));
}

// zero-pad per-head 624 -> 640 cols: in [128,4992] float, out [128,5120] half
__global__ void pad_w_k(const float* __restrict__ in, __half* __restrict__ out)
{
    int idx = blockIdx.x * blockDim.x + threadIdx.x;
    if (idx >= DKV * NH * DH) return;
    int i = idx / (NH * DH);
    int c = idx % (NH * DH);
    int h = c / DH, d = c % DH;
    float v = (d < SPLITD) ? in[(size_t)i * (NH * SPLITD) + h * SPLITD + d] : 0.0f;
    out[idx] = __float2half_rn(v);
}

// bias2[n] = outb[n] + sum_m buv[m]*Wout[m,n]   (block per n, 256-thread reduce)
__global__ __launch_bounds__(256)
void bias2_k(const float* __restrict__ outw, const float* __restrict__ outb,
             const float* __restrict__ buv, float* __restrict__ o)
{
    int n = blockIdx.x;
    int t = threadIdx.x;
    float s = 0.0f;
    for (int m = t; m < DM; m += 256) s += buv[m] * outw[(size_t)m * DM + n];
    __shared__ float red[256];
    red[t] = s; __syncthreads();
    for (int off = 128; off > 0; off >>= 1) {
        if (t < off) red[t] += red[t + off];
        __syncthreads();
    }
    if (t == 0) o[n] = outb[n] + red[0];
}

// bqrow[h][n] = sum_d buq[h*624+d] * Wuk[n, h*624+d]
__global__ void bqrow_k(const float* __restrict__ buq, const float* __restrict__ wuk,
                        float* __restrict__ o)
{
    int idx = blockIdx.x * blockDim.x + threadIdx.x;
    if (idx >= NH * DKV) return;
    int h = idx / DKV, n = idx % DKV;
    float s = 0.0f;
    for (int d = 0; d < SPLITD; d++)
        s += buq[h * SPLITD + d] * wuk[(size_t)n * (NH * SPLITD) + h * SPLITD + d];
    o[idx] = s;
}

// wh[h][k] = sum_d Wuq[k, h*624+d]*buk[h*624+d];  sconst[h] = buq_h . buk_h
__global__ void wh_k(const float* __restrict__ wuq, const float* __restrict__ buk,
                     const float* __restrict__ buq, float* __restrict__ o, float* __restrict__ sc)
{
    int idx = blockIdx.x * blockDim.x + threadIdx.x;
    if (idx >= NH * DKV) return;
    int h = idx / DKV, k = idx % DKV;
    float s = 0.0f;
    for (int d = 0; d < SPLITD; d++)
        s += wuq[(size_t)k * (NH * SPLITD) + h * SPLITD + d] * buk[h * SPLITD + d];
    o[idx] = s;
    if (k == 0) {
        float c = 0.0f;
        for (int d = 0; d < SPLITD; d++) c += buq[h * SPLITD + d] * buk[h * SPLITD + d];
        sc[h] = c;
    }
}

// s_q column: qp[m, h*KP+144] = sconst[h] + sum_k cq[m,k]*wh[h,k]
__global__ void sq_k(const __half* __restrict__ cq, const float* __restrict__ wh,
                     const float* __restrict__ scst, __half* __restrict__ qp)
{
    int idx = blockIdx.x * blockDim.x + threadIdx.x;
    if (idx >= MROWS * NH) return;
    int m = idx / NH, h = idx % NH;
    float s = scst[h];
    for (int k = 0; k < DKV; k++)
        s += __half2float(cq[(size_t)m * DKV + k]) * wh[h * DKV + k];
    qp[(size_t)m * LDQP + h * KP + 144] = __float2half_rn(s);
}

// qp pad cols 145..159 = 0
__global__ void qppad_k(__half* __restrict__ qp)
{
    int idx = blockIdx.x * blockDim.x + threadIdx.x;
    if (idx >= MROWS * NH) return;
    int m = idx / NH, h = idx % NH;
    __half* p = qp + (size_t)m * LDQP + h * KP;
    for (int c = 145; c < KP; c++) p[c] = __float2half_rn(0.0f);
}

// kp fill: cols 0..127 = ckv[m], col 144 = 1, cols 145..159 = 0
__global__ void kpfill_k(const __half* __restrict__ ckv, __half* __restrict__ kp)
{
    int idx = blockIdx.x * blockDim.x + threadIdx.x;
    int total = MROWS * NH * 18;
    if (idx >= total) return;
    int c = idx % 18;
    int mh = idx / 18;
    int m = mh / NH, h = mh % NH;
    __half* p = kp + (size_t)m * LDQP + h * KP;
    if (c < 16) {
        uint4 v = *reinterpret_cast<const uint4*>(ckv + (size_t)m * DKV + c * 8);
        *reinterpret_cast<uint4*>(p + c * 8) = v;
    } else if (c == 16) {
        __half z = __float2half_rn(0.0f);
        __half vals[8] = { __float2half_rn(1.0f), z, z, z, z, z, z, z };
        *reinterpret_cast<uint4*>(p + 144) = *reinterpret_cast<uint4*>(vals);
    } else {
        __half z = __float2half_rn(0.0f);
        __half vals[8] = { z, z, z, z, z, z, z, z };
        *reinterpret_cast<uint4*>(p + 152) = *reinterpret_cast<uint4*>(vals);
    }
}

// RoPE: pre [4096,128] half -> dst[m*LDQP + h*KP + 128 + d]; optional float out
__global__ void rope_k(const __half* __restrict__ pre, __half* __restrict__ dst,
                       float* __restrict__ rout)
{
    int idx = blockIdx.x * blockDim.x + threadIdx.x;
    if (idx >= MROWS * DKV) return;
    int m = idx >> 7;
    int c = idx & 127;
    int h = c >> 4;
    int d = c & 15;
    int j = d & 7;
    int s = m & (SEQ - 1);
    float t = (float)s * (1.0f / 40.0f);
    float invf = __expf(-(float)j * 0.86346941f);  // ln(1000)/8
    float ang = t * invf;
    float sn, cs;
    sincosf(ang, &sn, &cs);
    float x = __half2float(pre[idx]);
    float p = __half2float(pre[(m << 7) + (h << 4) + ((d < 8) ? d + 8 : d - 8)]);
    float val = x * cs + ((d < 8) ? -p : p) * sn;
    dst[(size_t)m * LDQP + h * KP + 128 + d] = __float2half_rn(val);
    if (rout) rout[idx] = val;
}

// ---------------- softmax over rows of length SEQ (half) ----------------
__global__ __launch_bounds__(256) void softmax_k(__half* __restrict__ s)
{
    __half2* row = reinterpret_cast<__half2*>(s + (size_t)blockIdx.x * SEQ);
    int t = threadIdx.x;
    float v[8];
    float mx = -1e30f;
#pragma unroll
    for (int i = 0; i < 4; i++) {
        float2 f = __half22float2(row[t + i * 256]);
        v[2 * i] = f.x; v[2 * i + 1] = f.y;
        mx = fmaxf(mx, fmaxf(f.x, f.y));
    }
    __shared__ float red[256];
    red[t] = mx; __syncthreads();
    for (int off = 128; off > 0; off >>= 1) {
        if (t < off) red[t] = fmaxf(red[t], red[t + off]);
        __syncthreads();
    }
    mx = red[0]; __syncthreads();
    float sum = 0.0f;
#pragma unroll
    for (int i = 0; i < 8; i++) { v[i] = __expf(v[i] - mx); sum += v[i]; }
    red[t] = sum; __syncthreads();
    for (int off = 128; off > 0; off >>= 1) {
        if (t < off) red[t] += red[t + off];
        __syncthreads();
    }
    float inv = 1.0f / red[0];
#pragma unroll
    for (int i = 0; i < 4; i++)
        row[t + i * 256] = __floats2half2_rn(v[2 * i] * inv, v[2 * i + 1] * inv);
}

// ============================================================================
// host launcher
// ============================================================================
extern "C" void kernel_launch(void* const* d_in, const int* in_sizes, int n_in,
                              void* d_out, int out_size)
{
    const float* h    = (const float*)d_in[0];
    const float* Wdkv = (const float*)d_in[1];
    const float* bdkv = (const float*)d_in[2];
    const float* Wdq  = (const float*)d_in[3];
    const float* bdq  = (const float*)d_in[4];
    const float* Wuk  = (const float*)d_in[5];
    const float* buk  = (const float*)d_in[6];
    const float* Wuv  = (const float*)d_in[7];
    const float* buv  = (const float*)d_in[8];
    const float* Wuq  = (const float*)d_in[9];
    const float* buq  = (const float*)d_in[10];
    const float* Wqr  = (const float*)d_in[11];
    const float* bqr  = (const float*)d_in[12];
    const float* Wkr  = (const float*)d_in[13];
    const float* bkr  = (const float*)d_in[14];
    const float* outw = (const float*)d_in[15];
    const float* outb = (const float*)d_in[16];
    float* out = (float*)d_out;

    __half *hh, *ckvh, *cqh, *ckvt, *qrp, *krp, *qp, *kp, *sc, *u;
    __half *wt_dkv, *wt_dq, *wt_qr, *wt_kr, *wt_out, *wuv_h, *wuq_p, *wuk_p, *mt, *w2t;
    float *ckvf, *bias2, *bqrow, *wh, *scst;
    cudaGetSymbolAddress((void**)&hh,    g_hh);
    cudaGetSymbolAddress((void**)&ckvh,  g_ckvh);
    cudaGetSymbolAddress((void**)&cqh,   g_cqh);
    cudaGetSymbolAddress((void**)&ckvt,  g_ckvt);
    cudaGetSymbolAddress((void**)&qrp,   g_qrp);
    cudaGetSymbolAddress((void**)&krp,   g_krp);
    cudaGetSymbolAddress((void**)&qp,    g_qp);
    cudaGetSymbolAddress((void**)&kp,    g_kp);
    cudaGetSymbolAddress((void**)&sc,    g_sc);
    cudaGetSymbolAddress((void**)&u,     g_u);
    cudaGetSymbolAddress((void**)&ckvf,  g_ckvf);
    cudaGetSymbolAddress((void**)&wt_dkv, g_wt_dkv);
    cudaGetSymbolAddress((void**)&wt_dq,  g_wt_dq);
    cudaGetSymbolAddress((void**)&wt_qr,  g_wt_qr);
    cudaGetSymbolAddress((void**)&wt_kr,  g_wt_kr);
    cudaGetSymbolAddress((void**)&wt_out, g_wt_out);
    cudaGetSymbolAddress((void**)&wuv_h,  g_wuv_h);
    cudaGetSymbolAddress((void**)&wuq_p,  g_wuq_p);
    cudaGetSymbolAddress((void**)&wuk_p,  g_wuk_p);
    cudaGetSymbolAddress((void**)&mt,     g_mt);
    cudaGetSymbolAddress((void**)&w2t,    g_w2t);
    cudaGetSymbolAddress((void**)&bias2,  g_bias2);
    cudaGetSymbolAddress((void**)&bqrow,  g_bqrow);
    cudaGetSymbolAddress((void**)&wh,     g_wh);
    cudaGetSymbolAddress((void**)&scst,   g_sconst);

    dim3 b256(256);
    // ---- conversions / transposes / precompute inputs ----
    f2h_k<<<((size_t)MROWS * DM / 4 + 255) / 256, 256>>>(h, hh, MROWS * DM / 4);
    f2h_k<<<(DKV * DM / 4 + 255) / 256, 256>>>(Wuv, wuv_h, DKV * DM / 4);
    transpose_f2h<<<dim3(DKV/32, DM/32), b256>>>(Wdkv, wt_dkv, DKV, DM);
    transpose_f2h<<<dim3(DKV/32, DM/32), b256>>>(Wdq,  wt_dq,  DKV, DM);
    transpose_f2h<<<dim3(DKV/32, DKV/32), b256>>>(Wqr, wt_qr, DKV, DKV);
    transpose_f2h<<<dim3(DKV/32, DKV/32), b256>>>(Wkr, wt_kr, DKV, DKV);
    transpose_f2h<<<dim3(DM/32, DM/32), b256>>>(outw, wt_out, DM, DM);
    pad_w_k<<<(DKV * NH * DH + 255) / 256, 256>>>(Wuq, wuq_p);
    pad_w_k<<<(DKV * NH * DH + 255) / 256, 256>>>(Wuk, wuk_p);
    bias2_k<<<DM, 256>>>(outw, outb, buv, bias2);
    bqrow_k<<<(NH * DKV + 255) / 256, 256>>>(buq, Wuk, bqrow);
    wh_k<<<(NH * DKV + 255) / 256, 256>>>(Wuq, buk, buq, wh, scst);

    const size_t out_ckv_off  = (size_t)MROWS * DM;
    const size_t out_krot_off = out_ckv_off + (size_t)MROWS * DKV;
    bool full_out = (size_t)out_size >= out_krot_off + (size_t)MROWS * DKV;
    float* ckv_dst = full_out ? (out + out_ckv_off) : ckvf;

    dim3 blk(256);
    auto grd = [](int M, int N, int Z) { return dim3((unsigned)(N / 128), (unsigned)(M / 128), (unsigned)Z); };

    // ---- precompute Mt_h = Wuk_h Wuq_h^T  [8][128][128] ----
    hgemm<<<grd(DKV, DKV, NH), blk>>>(wuk_p, wuq_p, nullptr, mt, nullptr,
        DKV, DKV, DH, NH*DH, NH*DH, DKV, 1.0f,
        0, DH, 0, DH, 0, DKV*DKV, 0, NH);
    // ---- precompute W2t[n, h*128+j] = sum_d Wout[h*640+d, n] * Wuv[j, h*640+d] ----
    hgemm<<<grd(DM, DKV, NH), blk>>>(wt_out, wuv_h, nullptr, w2t, nullptr,
        DM, DKV, DH, DM, DM, NH*DKV, 1.0f,
        0, DH, 0, DH, 0, DKV, 0, NH);

    // 1) down projections
    hgemm<<<grd(MROWS, DKV, 1), blk>>>(hh, wt_dkv, ckv_dst, ckvh, bdkv,
        MROWS, DKV, DM, DM, DM, DKV, 1.0f, 0,0,0,0,0,0,0, 1);
    hgemm<<<grd(MROWS, DKV, 1), blk>>>(hh, wt_dq, nullptr, cqh, bdq,
        MROWS, DKV, DM, DM, DM, DKV, 1.0f, 0,0,0,0,0,0,0, 1);

    // 2) q-tilde = c_q Mt_h^T + bqrow_h  -> qp cols [h*KP .. h*KP+127]
    hgemm<<<grd(MROWS, DKV, NH), blk>>>(cqh, mt, nullptr, qp, bqrow,
        MROWS, DKV, DKV, DKV, DKV, LDQP, 1.0f,
        0, 0, 0, DKV*DKV, 0, KP, DKV, NH);

    // 3) rotary pre-projections
    hgemm<<<grd(MROWS, DKV, 1), blk>>>(cqh, wt_qr, nullptr, qrp, bqr,
        MROWS, DKV, DKV, DKV, DKV, DKV, 1.0f, 0,0,0,0,0,0,0, 1);
    hgemm<<<grd(MROWS, DKV, 1), blk>>>(ckvh, wt_kr, nullptr, krp, bkr,
        MROWS, DKV, DKV, DKV, DKV, DKV, 1.0f, 0,0,0,0,0,0,0, 1);

    // 4) assemble qp / kp
    rope_k<<<(MROWS * DKV + 255) / 256, 256>>>(qrp, qp, nullptr);
    rope_k<<<(MROWS * DKV + 255) / 256, 256>>>(krp, kp,
        full_out ? (out + out_krot_off) : nullptr);
    sq_k<<<(MROWS * NH + 255) / 256, 256>>>(cqh, wh, scst, qp);
    qppad_k<<<(MROWS * NH + 255) / 256, 256>>>(qp);
    kpfill_k<<<(MROWS * NH * 18 + 255) / 256, 256>>>(ckvh, kp);

    // 5) scores = qp . kp^T / sqrt(640)   [16][2048][2048]
    const long long SS = (long long)SEQ * SEQ;
    float inv_sqrt = 1.0f / sqrtf((float)DH);
    hgemm<<<grd(SEQ, SEQ, BATCH*NH), blk>>>(qp, kp, nullptr, sc, nullptr,
        SEQ, SEQ, KP, LDQP, LDQP, SEQ, inv_sqrt,
        (long long)SEQ * LDQP, KP, (long long)SEQ * LDQP, KP,
        (long long)NH * SS, SS, 0, NH);

    // 6) softmax
    softmax_k<<<BATCH * NH * SEQ, 256>>>(sc);

    // 7) ckv transpose per batch [2048,128] -> [128,2048]
    transpose_h2h<<<dim3(DKV/32, SEQ/32, BATCH), b256>>>(ckvh, ckvt, DKV, SEQ,
        (long long)SEQ * DKV, (long long)DKV * SEQ);

    // 8) u = attn . ckv   -> [b][s][h*128]
    hgemm<<<grd(SEQ, DKV, BATCH*NH), blk>>>(sc, ckvt, nullptr, u, nullptr,
        SEQ, DKV, SEQ, SEQ, SEQ, NH*DKV, 1.0f,
        (long long)NH * SS, SS, (long long)DKV * SEQ, 0,
        (long long)SEQ * NH * DKV, DKV, 0, NH);

    // 9) out = u @ W2t^T + bias2   [4096,5120]
    hgemm<<<grd(MROWS, DM, 1), blk>>>(u, w2t, out, nullptr, bias2,
        MROWS, DM, NH*DKV, NH*DKV, NH*DKV, DM, 1.0f, 0,0,0,0,0,0,0, 1);
}

// round 9
// speedup vs baseline: 2.2105x; 1.8851x over previous
#include <cuda_runtime.h>
#include <cuda_fp16.h>
#include <math.h>
#include <stdint.h>

// ---------------- problem constants ----------------
#define BATCH 2
#define SEQ   2048
#define DM    5120
#define NH    8
#define DH    640
#define DR    16
#define SPLITD 624
#define DKV   128
#define MROWS (BATCH*SEQ)        // 4096
#define KP    160                // per-head score K-dim: [128 ckv |16 rope |1 bias |15 pad]
#define LDQP  (NH*KP)            // 1280
#define NDD   256                // merged down-proj N: [ckv|cq]

// ---------------- scratch (device globals; no allocs allowed) ----------------
__device__ __align__(16) __half g_hh   [(size_t)MROWS*DM];
__device__ __align__(16) __half g_ckvcq[(size_t)MROWS*NDD];   // [ckv(0:128) | cq(128:256)]
__device__ __align__(16) __half g_krqrp[2*MROWS*DKV];          // [krp | qrp]
__device__ __align__(16) __half g_qp   [(size_t)MROWS*LDQP];
__device__ __align__(16) __half g_kp   [(size_t)MROWS*LDQP];
__device__ __align__(16) __half g_u    [(size_t)MROWS*NH*DKV]; // [4096,1024]
__device__ __align__(16) float  g_ckvf [MROWS*DKV];
// weights
__device__ __align__(16) __half g_wdd  [(size_t)NDD*DM];       // [wt_dkv; wt_dq] [256,5120]
__device__ __align__(16) __half g_wkq  [2*DKV*DKV];            // [wt_kr; wt_qr]
__device__ __align__(16) __half g_wt_out[(size_t)DM*DM];       // Wout^T [DM, NH*DH]
__device__ __align__(16) __half g_wuv_h [DKV*DM];
__device__ __align__(16) __half g_wuq_p [DKV*NH*DH];           // zero-padded 624->640
__device__ __align__(16) __half g_wuk_p [DKV*NH*DH];
__device__ __align__(16) __half g_mt    [NH*DKV*DKV];          // Mt_h = Wuk_h Wuq_h^T
__device__ __align__(16) __half g_w2t   [(size_t)DM*NH*DKV];   // [5120,1024]
__device__ __align__(16) float  g_bias2 [DM];
__device__ __align__(16) float  g_bqrow [NH*DKV];
__device__ __align__(16) float  g_wh    [NH*DKV];
__device__ __align__(16) float  g_sconst[NH];
__device__ __align__(16) float  g_bdd   [NDD];
__device__ __align__(16) float  g_bkq   [2*DKV];

// ---------------- PTX helpers ----------------
__device__ __forceinline__ uint32_t smem_u32(const void* p) {
    uint32_t a;
    asm("{ .reg .u64 t; cvta.to.shared.u64 t, %1; cvt.u32.u64 %0, t; }" : "=r"(a) : "l"(p));
    return a;
}
__device__ __forceinline__ void cp16(uint32_t dst, const void* src) {
    asm volatile("cp.async.cg.shared.global [%0], [%1], 16;" :: "r"(dst), "l"(src) : "memory");
}
#define CP_COMMIT() asm volatile("cp.async.commit_group;" ::: "memory")
#define CP_WAIT(n)  asm volatile("cp.async.wait_group %0;" :: "n"(n) : "memory")

__device__ __forceinline__ void ldm_x4(uint32_t* r, uint32_t addr) {
    asm volatile("ldmatrix.sync.aligned.m8n8.x4.shared.b16 {%0,%1,%2,%3}, [%4];"
                 : "=r"(r[0]), "=r"(r[1]), "=r"(r[2]), "=r"(r[3]) : "r"(addr));
}
__device__ __forceinline__ void ldm_x4t(uint32_t* r, uint32_t addr) {
    asm volatile("ldmatrix.sync.aligned.m8n8.x4.trans.shared.b16 {%0,%1,%2,%3}, [%4];"
                 : "=r"(r[0]), "=r"(r[1]), "=r"(r[2]), "=r"(r[3]) : "r"(addr));
}
__device__ __forceinline__ void mma_f16(float* c, const uint32_t* a, uint32_t b0, uint32_t b1) {
    asm volatile("mma.sync.aligned.m16n8k16.row.col.f32.f16.f16.f32 "
                 "{%0,%1,%2,%3}, {%4,%5,%6,%7}, {%8,%9}, {%0,%1,%2,%3};"
                 : "+f"(c[0]), "+f"(c[1]), "+f"(c[2]), "+f"(c[3])
                 : "r"(a[0]), "r"(a[1]), "r"(a[2]), "r"(a[3]), "r"(b0), "r"(b1));
}
__device__ __forceinline__ uint32_t packh2(float x, float y) {
    __half2 h = __floats2half2_rn(x, y);
    return *reinterpret_cast<uint32_t*>(&h);
}

// ============================================================================
// fp16 mma.sync GEMM: C = alpha*A*B^T + bias. 128x128 tile, BK=32, 2-stage.
// Cf written only for cols < cfN (ld ldcf); Ch full (ld ldc).
// ============================================================================
#define SPADH 40

__global__ __launch_bounds__(256)
void hgemm(const __half* __restrict__ A, const __half* __restrict__ B,
           float* __restrict__ Cf, __half* __restrict__ Ch,
           const float* __restrict__ bias,
           int M, int N, int K, int lda, int ldb, int ldc, int ldcf, int cfN,
           float alpha,
           long long sAhi, long long sAlo, long long sBhi, long long sBlo,
           long long sChi, long long sClo, long long sBiasLo, int zdiv)
{
    __shared__ __half As[2][128][SPADH];
    __shared__ __half Bs[2][128][SPADH];

    int tid  = threadIdx.x;
    int warp = tid >> 5;
    int lane = tid & 31;
    int wr = warp >> 1;
    int wc = warp & 1;
    int qid = lane >> 2;
    int tig = lane & 3;

    int z  = blockIdx.z;
    int zh = z / zdiv, zl = z % zdiv;
    A += zh * sAhi + zl * sAlo;
    B += zh * sBhi + zl * sBlo;
    long long cofs = zh * sChi + zl * sClo;
    if (Cf) Cf += cofs;
    if (Ch) Ch += cofs;
    if (bias) bias += zl * sBiasLo;

    int row0 = blockIdx.y * 128, col0 = blockIdx.x * 128;
    const __half* Ab = A + (size_t)row0 * lda;
    const __half* Bb = B + (size_t)col0 * ldb;

    int r0 = tid >> 2, cc = (tid & 3) * 8;
    int r1 = r0 + 64;
    uint32_t dA0[2], dA1[2], dB0[2], dB1[2];
#pragma unroll
    for (int s = 0; s < 2; s++) {
        dA0[s] = smem_u32(&As[s][r0][cc]);
        dA1[s] = smem_u32(&As[s][r1][cc]);
        dB0[s] = smem_u32(&Bs[s][r0][cc]);
        dB1[s] = smem_u32(&Bs[s][r1][cc]);
    }
    uint32_t aAddr[2][2], bAddr[2][4];
#pragma unroll
    for (int s = 0; s < 2; s++) {
#pragma unroll
        for (int mi = 0; mi < 2; mi++)
            aAddr[s][mi] = smem_u32(&As[s][wr * 32 + mi * 16 + (lane & 15)][(lane >> 4) * 8]);
#pragma unroll
        for (int np = 0; np < 4; np++)
            bAddr[s][np] = smem_u32(&Bs[s][wc * 64 + np * 16 + (lane & 7) + ((lane >> 4) & 1) * 8]
                                        [((lane >> 3) & 1) * 8]);
    }

    float acc[2][8][4];
#pragma unroll
    for (int mi = 0; mi < 2; mi++)
#pragma unroll
        for (int ni = 0; ni < 8; ni++)
#pragma unroll
            for (int i = 0; i < 4; i++) acc[mi][ni][i] = 0.0f;

    int T = K >> 5;

    cp16(dA0[0], Ab + (size_t)r0 * lda + cc);
    cp16(dA1[0], Ab + (size_t)r1 * lda + cc);
    cp16(dB0[0], Bb + (size_t)r0 * ldb + cc);
    cp16(dB1[0], Bb + (size_t)r1 * ldb + cc);
    CP_COMMIT();

    for (int t = 0; t < T; t++) {
        if (t + 1 < T) {
            int s = (t + 1) & 1;
            int k0 = (t + 1) * 32;
            cp16(dA0[s], Ab + (size_t)r0 * lda + k0 + cc);
            cp16(dA1[s], Ab + (size_t)r1 * lda + k0 + cc);
            cp16(dB0[s], Bb + (size_t)r0 * ldb + k0 + cc);
            cp16(dB1[s], Bb + (size_t)r1 * ldb + k0 + cc);
            CP_COMMIT();
            CP_WAIT(1);
        } else {
            CP_WAIT(0);
        }
        __syncthreads();

        int s = t & 1;
#pragma unroll
        for (int ks = 0; ks < 2; ks++) {
            uint32_t koff = ks * 32;
            uint32_t a[2][4], b[16];
#pragma unroll
            for (int mi = 0; mi < 2; mi++) ldm_x4(a[mi], aAddr[s][mi] + koff);
#pragma unroll
            for (int np = 0; np < 4; np++) ldm_x4(b + np * 4, bAddr[s][np] + koff);
#pragma unroll
            for (int ni = 0; ni < 8; ni++) {
                uint32_t b0 = b[(ni >> 1) * 4 + (ni & 1) * 2];
                uint32_t b1 = b[(ni >> 1) * 4 + (ni & 1) * 2 + 1];
                mma_f16(acc[0][ni], a[0], b0, b1);
                mma_f16(acc[1][ni], a[1], b0, b1);
            }
        }
        __syncthreads();
    }

#pragma unroll
    for (int mi = 0; mi < 2; mi++) {
        int rg = row0 + wr * 32 + mi * 16 + qid;
#pragma unroll
        for (int ni = 0; ni < 8; ni++) {
            int cg = col0 + wc * 64 + ni * 8 + tig * 2;
            float bx = 0.0f, by = 0.0f;
            if (bias) { bx = bias[cg]; by = bias[cg + 1]; }
            float o0 = alpha * acc[mi][ni][0] + bx;
            float o1 = alpha * acc[mi][ni][1] + by;
            float o2 = alpha * acc[mi][ni][2] + bx;
            float o3 = alpha * acc[mi][ni][3] + by;
            if (Cf && cg < cfN) {
                *reinterpret_cast<float2*>(Cf + (size_t)rg * ldcf + cg)       = make_float2(o0, o1);
                *reinterpret_cast<float2*>(Cf + (size_t)(rg + 8) * ldcf + cg) = make_float2(o2, o3);
            }
            if (Ch) {
                *reinterpret_cast<__half2*>(Ch + (size_t)rg * ldc + cg)       = __floats2half2_rn(o0, o1);
                *reinterpret_cast<__half2*>(Ch + (size_t)(rg + 8) * ldc + cg) = __floats2half2_rn(o2, o3);
            }
        }
    }
}

// ============================================================================
// flash attention: per CTA = (q-tile 128 rows, one (b,h)). online softmax.
// u[m, h*128+n] = softmax(qp_h . kp_h^T * scale) @ ckv
// ============================================================================
#define FAQ_LD 168
#define FAV_LD 136
#define FA_SMEM ((3*128*FAQ_LD + 2*128*FAV_LD) * 2)   // 198656 B

__global__ __launch_bounds__(256, 1)
void flash_k(const __half* __restrict__ qp, const __half* __restrict__ kp,
             const __half* __restrict__ ckv, int ldckv,
             __half* __restrict__ u, float scale)
{
    extern __shared__ __half sm[];
    __half* Qs = sm;                        // [128][168]
    __half* Ks = sm + 128 * FAQ_LD;         // [2][128][168]
    __half* Vs = sm + 3 * 128 * FAQ_LD;     // [2][128][136]

    int tid = threadIdx.x;
    int warp = tid >> 5, lane = tid & 31;
    int qid = lane >> 2, tig = lane & 3;

    int qt = blockIdx.x;   // 0..15
    int z  = blockIdx.y;   // 0..15
    int b = z >> 3, h = z & 7;

    const __half* Qg = qp + ((size_t)(b * SEQ + qt * 128)) * LDQP + h * KP;
    const __half* Kg = kp + ((size_t)b * SEQ) * LDQP + h * KP;
    const __half* Vg = ckv + ((size_t)b * SEQ) * ldckv;

    // ---- load Q + K0 + V0 ----
#pragma unroll
    for (int i = 0; i < 10; i++) {
        int idx = tid + i * 256;
        int r = idx / 20, c = idx % 20;
        cp16(smem_u32(Qs + r * FAQ_LD + c * 8), Qg + (size_t)r * LDQP + c * 8);
    }
#pragma unroll
    for (int i = 0; i < 10; i++) {
        int idx = tid + i * 256;
        int r = idx / 20, c = idx % 20;
        cp16(smem_u32(Ks + r * FAQ_LD + c * 8), Kg + (size_t)r * LDQP + c * 8);
    }
#pragma unroll
    for (int i = 0; i < 8; i++) {
        int idx = tid + i * 256;
        int r = idx / 16, c = idx % 16;
        cp16(smem_u32(Vs + r * FAV_LD + c * 8), Vg + (size_t)r * ldckv + c * 8);
    }
    CP_COMMIT();

    uint32_t qAddr = smem_u32(Qs + (warp * 16 + (lane & 15)) * FAQ_LD + (lane >> 4) * 8);
    uint32_t kAddr[2][8], vAddr[2][8];
#pragma unroll
    for (int s = 0; s < 2; s++) {
#pragma unroll
        for (int nb = 0; nb < 8; nb++) {
            kAddr[s][nb] = smem_u32(Ks + s * 128 * FAQ_LD
                + (nb * 16 + (lane & 7) + ((lane >> 4) & 1) * 8) * FAQ_LD
                + ((lane >> 3) & 1) * 8);
            vAddr[s][nb] = smem_u32(Vs + s * 128 * FAV_LD
                + (lane & 15) * FAV_LD
                + nb * 16 + ((lane >> 4) << 3));
        }
    }

    float oacc[16][4];
#pragma unroll
    for (int j = 0; j < 16; j++)
#pragma unroll
        for (int i = 0; i < 4; i++) oacc[j][i] = 0.0f;
    float m0 = -1e30f, m1 = -1e30f, l0 = 0.0f, l1 = 0.0f;

    for (int kt = 0; kt < 16; kt++) {
        CP_WAIT(0);
        __syncthreads();
        if (kt + 1 < 16) {
            int s = (kt + 1) & 1;
            const __half* Kt = Kg + (size_t)(kt + 1) * 128 * LDQP;
            const __half* Vt = Vg + (size_t)(kt + 1) * 128 * ldckv;
#pragma unroll
            for (int i = 0; i < 10; i++) {
                int idx = tid + i * 256;
                int r = idx / 20, c = idx % 20;
                cp16(smem_u32(Ks + s * 128 * FAQ_LD + r * FAQ_LD + c * 8),
                     Kt + (size_t)r * LDQP + c * 8);
            }
#pragma unroll
            for (int i = 0; i < 8; i++) {
                int idx = tid + i * 256;
                int r = idx / 16, c = idx % 16;
                cp16(smem_u32(Vs + s * 128 * FAV_LD + r * FAV_LD + c * 8),
                     Vt + (size_t)r * ldckv + c * 8);
            }
            CP_COMMIT();
        }

        int s = kt & 1;
        float sacc[16][4];
#pragma unroll
        for (int j = 0; j < 16; j++)
#pragma unroll
            for (int i = 0; i < 4; i++) sacc[j][i] = 0.0f;
#pragma unroll
        for (int ks = 0; ks < 10; ks++) {
            uint32_t a[4];
            ldm_x4(a, qAddr + ks * 32);
#pragma unroll
            for (int nb = 0; nb < 8; nb++) {
                uint32_t bb[4];
                ldm_x4(bb, kAddr[s][nb] + ks * 32);
                mma_f16(sacc[2 * nb],     a, bb[0], bb[1]);
                mma_f16(sacc[2 * nb + 1], a, bb[2], bb[3]);
            }
        }
        float mx0 = -1e30f, mx1 = -1e30f;
#pragma unroll
        for (int j = 0; j < 16; j++) {
            sacc[j][0] *= scale; sacc[j][1] *= scale;
            sacc[j][2] *= scale; sacc[j][3] *= scale;
            mx0 = fmaxf(mx0, fmaxf(sacc[j][0], sacc[j][1]));
            mx1 = fmaxf(mx1, fmaxf(sacc[j][2], sacc[j][3]));
        }
        mx0 = fmaxf(mx0, __shfl_xor_sync(0xFFFFFFFF, mx0, 1));
        mx0 = fmaxf(mx0, __shfl_xor_sync(0xFFFFFFFF, mx0, 2));
        mx1 = fmaxf(mx1, __shfl_xor_sync(0xFFFFFFFF, mx1, 1));
        mx1 = fmaxf(mx1, __shfl_xor_sync(0xFFFFFFFF, mx1, 2));
        float mn0 = fmaxf(m0, mx0), mn1 = fmaxf(m1, mx1);
        float f0 = __expf(m0 - mn0), f1 = __expf(m1 - mn1);
        m0 = mn0; m1 = mn1;
        float ts0 = 0.0f, ts1 = 0.0f;
#pragma unroll
        for (int j = 0; j < 16; j++) {
            sacc[j][0] = __expf(sacc[j][0] - m0);
            sacc[j][1] = __expf(sacc[j][1] - m0);
            sacc[j][2] = __expf(sacc[j][2] - m1);
            sacc[j][3] = __expf(sacc[j][3] - m1);
            ts0 += sacc[j][0] + sacc[j][1];
            ts1 += sacc[j][2] + sacc[j][3];
        }
        ts0 += __shfl_xor_sync(0xFFFFFFFF, ts0, 1);
        ts0 += __shfl_xor_sync(0xFFFFFFFF, ts0, 2);
        ts1 += __shfl_xor_sync(0xFFFFFFFF, ts1, 1);
        ts1 += __shfl_xor_sync(0xFFFFFFFF, ts1, 2);
        l0 = l0 * f0 + ts0;
        l1 = l1 * f1 + ts1;
#pragma unroll
        for (int j = 0; j < 16; j++) {
            oacc[j][0] *= f0; oacc[j][1] *= f0;
            oacc[j][2] *= f1; oacc[j][3] *= f1;
        }
#pragma unroll
        for (int kb = 0; kb < 8; kb++) {
            uint32_t a[4];
            a[0] = packh2(sacc[2 * kb][0],     sacc[2 * kb][1]);
            a[1] = packh2(sacc[2 * kb][2],     sacc[2 * kb][3]);
            a[2] = packh2(sacc[2 * kb + 1][0], sacc[2 * kb + 1][1]);
            a[3] = packh2(sacc[2 * kb + 1][2], sacc[2 * kb + 1][3]);
            uint32_t voff = (uint32_t)(kb * 16 * FAV_LD * 2);
#pragma unroll
            for (int nb = 0; nb < 8; nb++) {
                uint32_t bb[4];
                ldm_x4t(bb, vAddr[s][nb] + voff);
                mma_f16(oacc[2 * nb],     a, bb[0], bb[1]);
                mma_f16(oacc[2 * nb + 1], a, bb[2], bb[3]);
            }
        }
    }

    float il0 = 1.0f / l0, il1 = 1.0f / l1;
    int rowg = b * SEQ + qt * 128 + warp * 16;
#pragma unroll
    for (int j = 0; j < 16; j++) {
        int col = h * 128 + j * 8 + tig * 2;
        *reinterpret_cast<__half2*>(u + (size_t)(rowg + qid) * (NH * DKV) + col)
            = __floats2half2_rn(oacc[j][0] * il0, oacc[j][1] * il0);
        *reinterpret_cast<__half2*>(u + (size_t)(rowg + qid + 8) * (NH * DKV) + col)
            = __floats2half2_rn(oacc[j][2] * il1, oacc[j][3] * il1);
    }
}

// ============================================================================
// small kernels
// ============================================================================
__global__ __launch_bounds__(256)
void transpose_f2h(const float* __restrict__ in, __half* __restrict__ out, int ldi, int ldo)
{
    __shared__ float t[32][33];
    int bx = blockIdx.x * 32, by = blockIdx.y * 32;
    int tx = threadIdx.x & 31, ty = threadIdx.x >> 5;
#pragma unroll
    for (int i = 0; i < 4; i++)
        t[ty + 8 * i][tx] = in[(size_t)(by + ty + 8 * i) * ldi + bx + tx];
    __syncthreads();
#pragma unroll
    for (int i = 0; i < 4; i++)
        out[(size_t)(bx + ty + 8 * i) * ldo + by + tx] = __float2half_rn(t[tx][ty + 8 * i]);
}

__global__ void f2h_k(const float* __restrict__ in, __half* __restrict__ out, int n4)
{
    int i = blockIdx.x * blockDim.x + threadIdx.x;
    if (i >= n4) return;
    float4 v = *reinterpret_cast<const float4*>(in + (size_t)i * 4);
    __half2 a = __floats2half2_rn(v.x, v.y);
    __half2 b = __floats2half2_rn(v.z, v.w);
    *reinterpret_cast<uint2*>(out + (size_t)i * 4) = make_uint2(
        *reinterpret_cast<uint32_t*>(&a), *reinterpret_cast<uint32_t*>(&b));
}

__global__ void pad_w_k(const float* __restrict__ in, __half* __restrict__ out)
{
    int idx = blockIdx.x * blockDim.x + threadIdx.x;
    if (idx >= DKV * NH * DH) return;
    int i = idx / (NH * DH);
    int c = idx % (NH * DH);
    int h = c / DH, d = c % DH;
    float v = (d < SPLITD) ? in[(size_t)i * (NH * SPLITD) + h * SPLITD + d] : 0.0f;
    out[idx] = __float2half_rn(v);
}

__global__ __launch_bounds__(256)
void bias2_k(const float* __restrict__ outw, const float* __restrict__ outb,
             const float* __restrict__ buv, float* __restrict__ o)
{
    int n = blockIdx.x;
    int t = threadIdx.x;
    float s = 0.0f;
    for (int m = t; m < DM; m += 256) s += buv[m] * outw[(size_t)m * DM + n];
    __shared__ float red[256];
    red[t] = s; __syncthreads();
    for (int off = 128; off > 0; off >>= 1) {
        if (t < off) red[t] += red[t + off];
        __syncthreads();
    }
    if (t == 0) o[n] = outb[n] + red[0];
}

__global__ void bqrow_k(const float* __restrict__ buq, const float* __restrict__ wuk,
                        float* __restrict__ o)
{
    int idx = blockIdx.x * blockDim.x + threadIdx.x;
    if (idx >= NH * DKV) return;
    int h = idx / DKV, n = idx % DKV;
    float s = 0.0f;
    for (int d = 0; d < SPLITD; d++)
        s += buq[h * SPLITD + d] * wuk[(size_t)n * (NH * SPLITD) + h * SPLITD + d];
    o[idx] = s;
}

__global__ void wh_k(const float* __restrict__ wuq, const float* __restrict__ buk,
                     const float* __restrict__ buq, float* __restrict__ o, float* __restrict__ sc)
{
    int idx = blockIdx.x * blockDim.x + threadIdx.x;
    if (idx >= NH * DKV) return;
    int h = idx / DKV, k = idx % DKV;
    float s = 0.0f;
    for (int d = 0; d < SPLITD; d++)
        s += wuq[(size_t)k * (NH * SPLITD) + h * SPLITD + d] * buk[h * SPLITD + d];
    o[idx] = s;
    if (k == 0) {
        float c = 0.0f;
        for (int d = 0; d < SPLITD; d++) c += buq[h * SPLITD + d] * buk[h * SPLITD + d];
        sc[h] = c;
    }
}

__global__ void bias_cat2(const float* a, const float* b, float* o, int n1, int n2)
{
    int i = blockIdx.x * blockDim.x + threadIdx.x;
    if (i >= n1 + n2) return;
    o[i] = (i < n1) ? a[i] : b[i - n1];
}

__global__ void sq_k(const __half* __restrict__ cq, int ldcq, const float* __restrict__ wh,
                     const float* __restrict__ scst, __half* __restrict__ qp)
{
    int idx = blockIdx.x * blockDim.x + threadIdx.x;
    if (idx >= MROWS * NH) return;
    int m = idx / NH, h = idx % NH;
    float s = scst[h];
    for (int k = 0; k < DKV; k++)
        s += __half2float(cq[(size_t)m * ldcq + k]) * wh[h * DKV + k];
    qp[(size_t)m * LDQP + h * KP + 144] = __float2half_rn(s);
}

__global__ void qppad_k(__half* __restrict__ qp)
{
    int idx = blockIdx.x * blockDim.x + threadIdx.x;
    if (idx >= MROWS * NH) return;
    int m = idx / NH, h = idx % NH;
    __half* p = qp + (size_t)m * LDQP + h * KP;
    for (int c = 145; c < KP; c++) p[c] = __float2half_rn(0.0f);
}

__global__ void kpfill_k(const __half* __restrict__ ckv, int ldckv, __half* __restrict__ kp)
{
    int idx = blockIdx.x * blockDim.x + threadIdx.x;
    int total = MROWS * NH * 18;
    if (idx >= total) return;
    int c = idx % 18;
    int mh = idx / 18;
    int m = mh / NH, h = mh % NH;
    __half* p = kp + (size_t)m * LDQP + h * KP;
    if (c < 16) {
        uint4 v = *reinterpret_cast<const uint4*>(ckv + (size_t)m * ldckv + c * 8);
        *reinterpret_cast<uint4*>(p + c * 8) = v;
    } else if (c == 16) {
        __half z = __float2half_rn(0.0f);
        __half vals[8] = { __float2half_rn(1.0f), z, z, z, z, z, z, z };
        *reinterpret_cast<uint4*>(p + 144) = *reinterpret_cast<uint4*>(vals);
    } else {
        __half z = __float2half_rn(0.0f);
        __half vals[8] = { z, z, z, z, z, z, z, z };
        *reinterpret_cast<uint4*>(p + 152) = *reinterpret_cast<uint4*>(vals);
    }
}

__global__ void rope_k(const __half* __restrict__ pre, __half* __restrict__ dst,
                       float* __restrict__ rout)
{
    int idx = blockIdx.x * blockDim.x + threadIdx.x;
    if (idx >= MROWS * DKV) return;
    int m = idx >> 7;
    int c = idx & 127;
    int h = c >> 4;
    int d = c & 15;
    int j = d & 7;
    int s = m & (SEQ - 1);
    float t = (float)s * (1.0f / 40.0f);
    float invf = __expf(-(float)j * 0.86346941f);  // ln(1000)/8
    float ang = t * invf;
    float sn, cs;
    sincosf(ang, &sn, &cs);
    float x = __half2float(pre[idx]);
    float p = __half2float(pre[(m << 7) + (h << 4) + ((d < 8) ? d + 8 : d - 8)]);
    float val = x * cs + ((d < 8) ? -p : p) * sn;
    dst[(size_t)m * LDQP + h * KP + 128 + d] = __float2half_rn(val);
    if (rout) rout[idx] = val;
}

// ============================================================================
// host launcher
// ============================================================================
extern "C" void kernel_launch(void* const* d_in, const int* in_sizes, int n_in,
                              void* d_out, int out_size)
{
    const float* h    = (const float*)d_in[0];
    const float* Wdkv = (const float*)d_in[1];
    const float* bdkv = (const float*)d_in[2];
    const float* Wdq  = (const float*)d_in[3];
    const float* bdq  = (const float*)d_in[4];
    const float* Wuk  = (const float*)d_in[5];
    const float* buk  = (const float*)d_in[6];
    const float* Wuv  = (const float*)d_in[7];
    const float* buv  = (const float*)d_in[8];
    const float* Wuq  = (const float*)d_in[9];
    const float* buq  = (const float*)d_in[10];
    const float* Wqr  = (const float*)d_in[11];
    const float* bqr  = (const float*)d_in[12];
    const float* Wkr  = (const float*)d_in[13];
    const float* bkr  = (const float*)d_in[14];
    const float* outw = (const float*)d_in[15];
    const float* outb = (const float*)d_in[16];
    float* out = (float*)d_out;

    __half *hh, *ckvcq, *krqrp, *qp, *kp, *u;
    __half *wdd, *wkq, *wt_out, *wuv_h, *wuq_p, *wuk_p, *mt, *w2t;
    float *ckvf, *bias2, *bqrow, *wh, *scst, *bdd, *bkq;
    cudaGetSymbolAddress((void**)&hh,    g_hh);
    cudaGetSymbolAddress((void**)&ckvcq, g_ckvcq);
    cudaGetSymbolAddress((void**)&krqrp, g_krqrp);
    cudaGetSymbolAddress((void**)&qp,    g_qp);
    cudaGetSymbolAddress((void**)&kp,    g_kp);
    cudaGetSymbolAddress((void**)&u,     g_u);
    cudaGetSymbolAddress((void**)&ckvf,  g_ckvf);
    cudaGetSymbolAddress((void**)&wdd,   g_wdd);
    cudaGetSymbolAddress((void**)&wkq,   g_wkq);
    cudaGetSymbolAddress((void**)&wt_out, g_wt_out);
    cudaGetSymbolAddress((void**)&wuv_h,  g_wuv_h);
    cudaGetSymbolAddress((void**)&wuq_p,  g_wuq_p);
    cudaGetSymbolAddress((void**)&wuk_p,  g_wuk_p);
    cudaGetSymbolAddress((void**)&mt,     g_mt);
    cudaGetSymbolAddress((void**)&w2t,    g_w2t);
    cudaGetSymbolAddress((void**)&bias2,  g_bias2);
    cudaGetSymbolAddress((void**)&bqrow,  g_bqrow);
    cudaGetSymbolAddress((void**)&wh,     g_wh);
    cudaGetSymbolAddress((void**)&scst,   g_sconst);
    cudaGetSymbolAddress((void**)&bdd,    g_bdd);
    cudaGetSymbolAddress((void**)&bkq,    g_bkq);

    cudaFuncSetAttribute(flash_k, cudaFuncAttributeMaxDynamicSharedMemorySize, FA_SMEM);

    dim3 b256(256);
    f2h_k<<<((size_t)MROWS * DM / 4 + 255) / 256, 256>>>(h, hh, MROWS * DM / 4);
    f2h_k<<<(DKV * DM / 4 + 255) / 256, 256>>>(Wuv, wuv_h, DKV * DM / 4);
    transpose_f2h<<<dim3(DKV/32, DM/32), b256>>>(Wdkv, wdd,                 DKV, DM);
    transpose_f2h<<<dim3(DKV/32, DM/32), b256>>>(Wdq,  wdd + (size_t)DKV*DM, DKV, DM);
    transpose_f2h<<<dim3(DKV/32, DKV/32), b256>>>(Wkr, wkq,                 DKV, DKV);
    transpose_f2h<<<dim3(DKV/32, DKV/32), b256>>>(Wqr, wkq + DKV*DKV,       DKV, DKV);
    transpose_f2h<<<dim3(DM/32, DM/32), b256>>>(outw, wt_out, DM, DM);
    pad_w_k<<<(DKV * NH * DH + 255) / 256, 256>>>(Wuq, wuq_p);
    pad_w_k<<<(DKV * NH * DH + 255) / 256, 256>>>(Wuk, wuk_p);
    bias2_k<<<DM, 256>>>(outw, outb, buv, bias2);
    bqrow_k<<<(NH * DKV + 255) / 256, 256>>>(buq, Wuk, bqrow);
    wh_k<<<(NH * DKV + 255) / 256, 256>>>(Wuq, buk, buq, wh, scst);
    bias_cat2<<<(NDD + 255) / 256, 256>>>(bdkv, bdq, bdd, DKV, DKV);
    bias_cat2<<<(2 * DKV + 255) / 256, 256>>>(bkr, bqr, bkq, DKV, DKV);

    const size_t out_ckv_off  = (size_t)MROWS * DM;
    const size_t out_krot_off = out_ckv_off + (size_t)MROWS * DKV;
    bool full_out = (size_t)out_size >= out_krot_off + (size_t)MROWS * DKV;
    float* ckv_dst = full_out ? (out + out_ckv_off) : ckvf;

    dim3 blk(256);
    auto grd = [](int M, int N, int Z) { return dim3((unsigned)(N / 128), (unsigned)(M / 128), (unsigned)Z); };

    // precompute Mt_h = Wuk_h Wuq_h^T  [8][128][128]
    hgemm<<<grd(DKV, DKV, NH), blk>>>(wuk_p, wuq_p, nullptr, mt, nullptr,
        DKV, DKV, DH, NH*DH, NH*DH, DKV, DKV, 0, 1.0f,
        0, DH, 0, DH, 0, DKV*DKV, 0, NH);
    // precompute W2t[n, h*128+j] = sum_d Wout^T[n, h*640+d] * Wuv[j, h*640+d]
    hgemm<<<grd(DM, DKV, NH), blk>>>(wt_out, wuv_h, nullptr, w2t, nullptr,
        DM, DKV, DH, DM, DM, NH*DKV, NH*DKV, 0, 1.0f,
        0, DH, 0, DH, 0, DKV, 0, NH);

    // 1) merged down projection: [ckv|cq] = h @ [Wdkv|Wdq] ; float ckv to output
    hgemm<<<grd(MROWS, NDD, 1), blk>>>(hh, wdd, ckv_dst, ckvcq, bdd,
        MROWS, NDD, DM, DM, DM, NDD, DKV, DKV, 1.0f, 0,0,0,0,0,0,0, 1);

    // 2) merged rotary pre-projections: z=0: krp = ckv@Wkr^T; z=1: qrp = cq@Wqr^T
    hgemm<<<grd(MROWS, DKV, 2), blk>>>(ckvcq, wkq, nullptr, krqrp, bkq,
        MROWS, DKV, DKV, NDD, DKV, DKV, DKV, 0, 1.0f,
        0, DKV, 0, DKV*DKV, 0, (long long)MROWS*DKV, DKV, 2);

    // 3) q-tilde = cq @ Mt_h^T + bqrow_h  -> qp cols [h*KP .. h*KP+127]
    hgemm<<<grd(MROWS, DKV, NH), blk>>>(ckvcq + DKV, mt, nullptr, qp, bqrow,
        MROWS, DKV, DKV, NDD, DKV, LDQP, LDQP, 0, 1.0f,
        0, 0, 0, DKV*DKV, 0, KP, DKV, NH);

    // 4) assemble qp / kp
    rope_k<<<(MROWS * DKV + 255) / 256, 256>>>(krqrp + (size_t)MROWS * DKV, qp, nullptr);
    rope_k<<<(MROWS * DKV + 255) / 256, 256>>>(krqrp, kp,
        full_out ? (out + out_krot_off) : nullptr);
    sq_k<<<(MROWS * NH + 255) / 256, 256>>>(ckvcq + DKV, NDD, wh, scst, qp);
    qppad_k<<<(MROWS * NH + 255) / 256, 256>>>(qp);
    kpfill_k<<<(MROWS * NH * 18 + 255) / 256, 256>>>(ckvcq, NDD, kp);

    // 5) fused flash attention -> u [4096, 1024]
    float inv_sqrt = 1.0f / sqrtf((float)DH);
    flash_k<<<dim3(SEQ/128, BATCH*NH), blk, FA_SMEM>>>(qp, kp, ckvcq, NDD, u, inv_sqrt);

    // 6) out = u @ W2t^T + bias2   [4096,5120]   (cfN = DM — R8's bug was cfN=0 here)
    hgemm<<<grd(MROWS, DM, 1), blk>>>(u, w2t, out, nullptr, bias2,
        MROWS, DM, NH*DKV, NH*DKV, NH*DKV, DM, DM, DM, 1.0f, 0,0,0,0,0,0,0, 1);
}